// round 1
// baseline (speedup 1.0000x reference)
#include <cuda_runtime.h>
#include <math.h>

#define NN 1024
#define BB 16
#define TT 12
#define FFD 8
#define HH 64
#define HOR 12

// ---------------- scratch buffer (no allocations allowed) ----------------
constexpr size_t SZ_XENC = (size_t)TT * NN * BB * HH;   // encoded inputs [t][n][b][h]
constexpr size_t SZ_NBH  = (size_t)NN * BB * HH;        // [n][b][64]
constexpr size_t SZ_NB2H = (size_t)NN * BB * 2 * HH;    // [n][b][128]
constexpr size_t SZ_NN2  = (size_t)NN * NN;
constexpr size_t SZ_FB   = (size_t)NN * BB * 512;

constexpr size_t OFF_XENC = 0;
constexpr size_t OFF_H    = OFF_XENC + SZ_XENC;
constexpr size_t OFF_X    = OFF_H    + SZ_NBH;
constexpr size_t OFF_S1F  = OFF_X    + SZ_NB2H;
constexpr size_t OFF_S2F  = OFF_S1F  + SZ_NB2H;
constexpr size_t OFF_S1B  = OFF_S2F  + SZ_NB2H;
constexpr size_t OFF_S2B  = OFF_S1B  + SZ_NB2H;
constexpr size_t OFF_RH   = OFF_S2B  + SZ_NB2H;
constexpr size_t OFF_U    = OFF_RH   + SZ_NBH;
constexpr size_t OFF_T1F  = OFF_U    + SZ_NBH;
constexpr size_t OFF_T2F  = OFF_T1F  + SZ_NBH;
constexpr size_t OFF_T1B  = OFF_T2F  + SZ_NBH;
constexpr size_t OFF_T2B  = OFF_T1B  + SZ_NBH;
constexpr size_t OFF_PRU  = OFF_T2B  + SZ_NBH;                 // [16384,128]
constexpr size_t OFF_PC   = OFF_PRU  + (size_t)NN * BB * 128;  // [16384,64]
constexpr size_t OFF_AF   = OFF_PC   + SZ_NBH;
constexpr size_t OFF_AB   = OFF_AF   + SZ_NN2;
constexpr size_t OFF_WF   = OFF_AB   + SZ_NN2;
constexpr size_t OFF_WB   = OFF_WF   + SZ_NN2;
constexpr size_t OFF_D1F  = OFF_WB   + SZ_NN2;
constexpr size_t OFF_D2F  = OFF_D1F  + SZ_NBH;
constexpr size_t OFF_D1B  = OFF_D2F  + SZ_NBH;
constexpr size_t OFF_D2B  = OFF_D1B  + SZ_NBH;
constexpr size_t OFF_Z    = OFF_D2B  + SZ_NBH;
constexpr size_t OFF_FB   = OFF_Z    + SZ_NBH;
constexpr size_t OFF_WRU  = OFF_FB   + SZ_FB;          // packed [512,128] = [W_r | W_u]
constexpr size_t OFF_BRU  = OFF_WRU  + (size_t)512 * 128;
constexpr size_t OFF_RS   = OFF_BRU  + 128;
constexpr size_t OFF_CS   = OFF_RS   + NN;
constexpr size_t OFF_DEGD = OFF_CS   + NN;
constexpr size_t OFF_DEGS = OFF_DEGD + NN;
constexpr size_t TOTAL_F  = OFF_DEGS + NN;

__device__ float g_buf[TOTAL_F];

// ---------------- generic tiled SGEMM ----------------
// C[M,N] (+)= A[M,K] * B[K,N], row-major with leading dims. All dims are
// multiples of the tile sizes in this problem (no edge guards needed).
template<int BM, int BN, int BK, int TM, int TN, bool ACC>
__global__ __launch_bounds__((BM / TM) * (BN / TN))
void sgemm(int M, int N, int Kd,
           const float* __restrict__ A, int lda,
           const float* __restrict__ B, int ldb,
           float* __restrict__ C, int ldc)
{
    constexpr int NT = (BM / TM) * (BN / TN);
    __shared__ float As[BK][BM];
    __shared__ float Bs[BK][BN];

    const int tid = threadIdx.x;
    const int bm  = blockIdx.y * BM;
    const int bn  = blockIdx.x * BN;
    const int tx  = tid % (BN / TN);
    const int ty  = tid / (BN / TN);

    float acc[TM][TN];
#pragma unroll
    for (int i = 0; i < TM; i++)
#pragma unroll
        for (int j = 0; j < TN; j++) acc[i][j] = 0.f;

    constexpr int A4 = BM * BK / 4;
    constexpr int B4 = BK * BN / 4;

    for (int k0 = 0; k0 < Kd; k0 += BK) {
#pragma unroll
        for (int idx = tid; idx < A4; idx += NT) {
            int row = idx / (BK / 4), c4 = idx % (BK / 4);
            float4 v = *reinterpret_cast<const float4*>(
                &A[(size_t)(bm + row) * lda + k0 + c4 * 4]);
            As[c4 * 4 + 0][row] = v.x;
            As[c4 * 4 + 1][row] = v.y;
            As[c4 * 4 + 2][row] = v.z;
            As[c4 * 4 + 3][row] = v.w;
        }
#pragma unroll
        for (int idx = tid; idx < B4; idx += NT) {
            int row = idx / (BN / 4), c4 = idx % (BN / 4);
            *reinterpret_cast<float4*>(&Bs[row][c4 * 4]) =
                *reinterpret_cast<const float4*>(
                    &B[(size_t)(k0 + row) * ldb + bn + c4 * 4]);
        }
        __syncthreads();

#pragma unroll
        for (int k = 0; k < BK; k++) {
            float af[TM], bf[TN];
#pragma unroll
            for (int i = 0; i < TM; i += 4) {
                float4 v = *reinterpret_cast<const float4*>(&As[k][ty * TM + i]);
                af[i] = v.x; af[i + 1] = v.y; af[i + 2] = v.z; af[i + 3] = v.w;
            }
#pragma unroll
            for (int j = 0; j < TN; j += 4) {
                float4 v = *reinterpret_cast<const float4*>(&Bs[k][tx * TN + j]);
                bf[j] = v.x; bf[j + 1] = v.y; bf[j + 2] = v.z; bf[j + 3] = v.w;
            }
#pragma unroll
            for (int i = 0; i < TM; i++)
#pragma unroll
                for (int j = 0; j < TN; j++)
                    acc[i][j] += af[i] * bf[j];
        }
        __syncthreads();
    }

#pragma unroll
    for (int i = 0; i < TM; i++) {
        size_t roff = (size_t)(bm + ty * TM + i) * ldc + bn + tx * TN;
#pragma unroll
        for (int j = 0; j < TN; j += 4) {
            float4 v;
            if (ACC) {
                float4 o = *reinterpret_cast<const float4*>(&C[roff + j]);
                v.x = o.x + acc[i][j];     v.y = o.y + acc[i][j + 1];
                v.z = o.z + acc[i][j + 2]; v.w = o.w + acc[i][j + 3];
            } else {
                v.x = acc[i][j];     v.y = acc[i][j + 1];
                v.z = acc[i][j + 2]; v.w = acc[i][j + 3];
            }
            *reinterpret_cast<float4*>(&C[roff + j]) = v;
        }
    }
}

// ---------------- small kernels ----------------
__global__ void k_normprep(const float* __restrict__ adj,
                           float* __restrict__ rsum, float* __restrict__ csum) {
    int i = blockIdx.x, t = threadIdx.x;
    float rs = 0.f, cs = 0.f;
    for (int j = t; j < NN; j += blockDim.x) {
        rs += adj[(size_t)i * NN + j];
        cs += adj[(size_t)j * NN + i];
    }
    __shared__ float sr[256], sc[256];
    sr[t] = rs; sc[t] = cs; __syncthreads();
    for (int s = 128; s > 0; s >>= 1) {
        if (t < s) { sr[t] += sr[t + s]; sc[t] += sc[t + s]; }
        __syncthreads();
    }
    if (t == 0) { rsum[i] = sr[0]; csum[i] = sc[0]; }
}

__global__ void k_normalize(const float* __restrict__ adj,
                            const float* __restrict__ rsum, const float* __restrict__ csum,
                            float* __restrict__ Af, float* __restrict__ Ab) {
    size_t idx = (size_t)blockIdx.x * blockDim.x + threadIdx.x;
    int i = (int)(idx / NN), j = (int)(idx % NN);
    Af[idx] = adj[idx] / rsum[i];
    Ab[idx] = adj[(size_t)j * NN + i] / csum[i];
}

__global__ void k_encoder(const float* __restrict__ x, const float* __restrict__ We,
                          const float* __restrict__ be, const float* __restrict__ emb,
                          float* __restrict__ xenc) {
    int bid = blockIdx.x;
    int b = bid % BB;
    int n = (bid / BB) % NN;
    int t = bid / (BB * NN);
    __shared__ float xv[FFD];
    int h = threadIdx.x;
    if (h < FFD) xv[h] = x[(((size_t)b * TT + t) * NN + n) * FFD + h];
    __syncthreads();
    float s = be[h] + emb[(size_t)n * HH + h];
#pragma unroll
    for (int f = 0; f < FFD; f++) s += xv[f] * We[f * HH + h];
    xenc[(((size_t)t * NN + n) * BB + b) * HH + h] = s;
}

__global__ void k_packWru(const float* __restrict__ Wr, const float* __restrict__ Wu,
                          const float* __restrict__ br, const float* __restrict__ bu,
                          float* __restrict__ Wru, float* __restrict__ bru) {
    int i = blockIdx.x * blockDim.x + threadIdx.x;
    if (i < 512 * 128) {
        int k = i >> 7, j = i & 127;
        Wru[i] = (j < 64) ? Wr[k * 64 + j] : Wu[k * 64 + (j - 64)];
    }
    if (i < 128) bru[i] = (i < 64) ? br[i] : bu[i - 64];
}

__global__ void k_buildxh(const float* __restrict__ xenc_t, const float* __restrict__ h,
                          float* __restrict__ X) {
    int i = blockIdx.x * 256 + threadIdx.x;      // NN*BB*128
    int c = i & 127, nb = i >> 7;
    X[i] = (c < 64) ? xenc_t[nb * 64 + c] : h[nb * 64 + (c - 64)];
}

__global__ void k_biasfill(float* __restrict__ C, const float* __restrict__ bias,
                           int ncols) {
    int i = blockIdx.x * 256 + threadIdx.x;
    C[i] = bias[i % ncols];
}

__global__ void k_concat_ru(float* __restrict__ FB,
                            const float* __restrict__ S1f, const float* __restrict__ S2f,
                            const float* __restrict__ S1b, const float* __restrict__ S2b) {
    int i = blockIdx.x * 256 + threadIdx.x;      // NN*BB*512
    int k = i & 511, row = i >> 9;
    int s = k >> 7, c = k & 127;
    const float* p = (s == 0) ? S1f : (s == 1) ? S2f : (s == 2) ? S1b : S2b;
    FB[i] = p[(size_t)row * 128 + c];
}

__global__ void k_gates(const float* __restrict__ Pru, const float* __restrict__ h,
                        float* __restrict__ u_out, float* __restrict__ rh) {
    int i = blockIdx.x * 256 + threadIdx.x;      // NN*BB*64
    int hh = i & 63, row = i >> 6;
    float pr = Pru[(size_t)row * 128 + hh];
    float pu = Pru[(size_t)row * 128 + 64 + hh];
    float r = 1.f / (1.f + expf(-pr));
    float u = 1.f / (1.f + expf(-pu));
    u_out[i] = u;
    rh[i] = r * h[i];
}

__global__ void k_concat_c(float* __restrict__ FB,
                           const float* __restrict__ S1f, const float* __restrict__ T1f,
                           const float* __restrict__ S2f, const float* __restrict__ T2f,
                           const float* __restrict__ S1b, const float* __restrict__ T1b,
                           const float* __restrict__ S2b, const float* __restrict__ T2b) {
    int i = blockIdx.x * 256 + threadIdx.x;      // NN*BB*512
    int k = i & 511, row = i >> 9;
    int blk = k >> 6, c = k & 63;
    const float* p; int stride;
    switch (blk) {
        case 0: p = S1f; stride = 128; break;
        case 1: p = T1f; stride = 64;  break;
        case 2: p = S2f; stride = 128; break;
        case 3: p = T2f; stride = 64;  break;
        case 4: p = S1b; stride = 128; break;
        case 5: p = T1b; stride = 64;  break;
        case 6: p = S2b; stride = 128; break;
        default: p = T2b; stride = 64; break;
    }
    FB[i] = p[(size_t)row * stride + c];
}

__global__ void k_hupdate(float* __restrict__ h, const float* __restrict__ u,
                          const float* __restrict__ Pc) {
    int i = blockIdx.x * 256 + threadIdx.x;
    float c = tanhf(Pc[i]);
    float uu = u[i];
    h[i] = uu * h[i] + (1.f - uu) * c;
}

__global__ void k_deg(const int* __restrict__ src, const int* __restrict__ dst,
                      const float* __restrict__ w,
                      float* __restrict__ degd, float* __restrict__ degs, int E) {
    int e = blockIdx.x * 256 + threadIdx.x;
    if (e < E) {
        atomicAdd(&degd[dst[e]], w[e]);
        atomicAdd(&degs[src[e]], w[e]);
    }
}

__global__ void k_buildW(const int* __restrict__ src, const int* __restrict__ dst,
                         const float* __restrict__ w,
                         const float* __restrict__ degd, const float* __restrict__ degs,
                         float* __restrict__ Wf, float* __restrict__ Wb, int E) {
    int e = blockIdx.x * 256 + threadIdx.x;
    if (e < E) {
        int s = src[e], d = dst[e];
        float we = w[e];
        float dd = degd[d];
        float ds = degs[s];
        float wf = (dd > 0.f) ? we / dd : 0.f;
        float wb = (ds > 0.f) ? we / ds : 0.f;
        atomicAdd(&Wf[(size_t)d * NN + s], wf);
        atomicAdd(&Wb[(size_t)s * NN + d], wb);
    }
}

__global__ void k_concat_d(float* __restrict__ FB,
                           const float* __restrict__ h,
                           const float* __restrict__ D1f, const float* __restrict__ D2f,
                           const float* __restrict__ D1b, const float* __restrict__ D2b) {
    int i = blockIdx.x * 256 + threadIdx.x;      // NN*BB*320
    int k = i % 320, row = i / 320;
    int blk = k / 64, c = k % 64;
    const float* p = (blk == 0) ? h : (blk == 1) ? D1f : (blk == 2) ? D2f
                   : (blk == 3) ? D1b : D2b;
    FB[i] = p[(size_t)row * 64 + c];
}

__global__ void k_decoder(const float* __restrict__ z, const float* __restrict__ Wd,
                          const float* __restrict__ bd, float* __restrict__ out) {
    int nb = blockIdx.x;                         // n*16 + b
    int n = nb >> 4, b = nb & 15;
    int j = threadIdx.x;                         // 0..95 = t*8+f
    __shared__ float zv[HH];
    if (j < HH) zv[j] = z[(size_t)nb * HH + j];
    __syncthreads();
    float s = bd[j];
#pragma unroll 8
    for (int hh = 0; hh < HH; hh++) s += zv[hh] * Wd[hh * (HOR * FFD) + j];
    int t = j >> 3, f = j & 7;
    out[(((size_t)b * HOR + t) * NN + n) * FFD + f] = s;
}

// ---------------- driver ----------------
extern "C" void kernel_launch(void* const* d_in, const int* in_sizes, int n_in,
                              void* d_out, int out_size) {
    const float* x     = (const float*)d_in[0];
    const int*   ei    = (const int*)  d_in[1];
    const float* ew    = (const float*)d_in[2];
    const float* adj   = (const float*)d_in[3];
    const float* Wenc  = (const float*)d_in[4];
    const float* benc  = (const float*)d_in[5];
    const float* nemb  = (const float*)d_in[6];
    const float* Wr    = (const float*)d_in[7];
    const float* br    = (const float*)d_in[8];
    const float* Wu    = (const float*)d_in[9];
    const float* bu    = (const float*)d_in[10];
    const float* Wc    = (const float*)d_in[11];
    const float* bc    = (const float*)d_in[12];
    const float* Wdiff = (const float*)d_in[13];
    const float* bdiff = (const float*)d_in[14];
    const float* Wdec  = (const float*)d_in[15];
    const float* bdec  = (const float*)d_in[16];
    float* out = (float*)d_out;
    const int E = in_sizes[2];
    const int* src = ei;
    const int* dst = ei + E;

    float* buf = nullptr;
    cudaGetSymbolAddress((void**)&buf, g_buf);

    float* XENC = buf + OFF_XENC;
    float* H    = buf + OFF_H;
    float* X    = buf + OFF_X;
    float* S1F  = buf + OFF_S1F;
    float* S2F  = buf + OFF_S2F;
    float* S1B  = buf + OFF_S1B;
    float* S2B  = buf + OFF_S2B;
    float* RH   = buf + OFF_RH;
    float* U    = buf + OFF_U;
    float* T1F  = buf + OFF_T1F;
    float* T2F  = buf + OFF_T2F;
    float* T1B  = buf + OFF_T1B;
    float* T2B  = buf + OFF_T2B;
    float* PRU  = buf + OFF_PRU;
    float* PC   = buf + OFF_PC;
    float* AF   = buf + OFF_AF;
    float* AB   = buf + OFF_AB;
    float* WF   = buf + OFF_WF;
    float* WB   = buf + OFF_WB;
    float* D1F  = buf + OFF_D1F;
    float* D2F  = buf + OFF_D2F;
    float* D1B  = buf + OFF_D1B;
    float* D2B  = buf + OFF_D2B;
    float* Z    = buf + OFF_Z;
    float* FB   = buf + OFF_FB;
    float* WRU  = buf + OFF_WRU;
    float* BRU  = buf + OFF_BRU;
    float* RS   = buf + OFF_RS;
    float* CS   = buf + OFF_CS;
    float* DEGD = buf + OFF_DEGD;
    float* DEGS = buf + OFF_DEGS;

    // supports + encoder + packed r/u weights
    k_normprep<<<NN, 256>>>(adj, RS, CS);
    k_normalize<<<(int)(SZ_NN2 / 256), 256>>>(adj, RS, CS, AF, AB);
    k_encoder<<<TT * NN * BB, 64>>>(x, Wenc, benc, nemb, XENC);
    k_packWru<<<(512 * 128 + 255) / 256, 256>>>(Wr, Wu, br, bu, WRU, BRU);
    cudaMemsetAsync(H, 0, SZ_NBH * sizeof(float));

    const dim3 gBig(2048 / 128, 1024 / 128);   // N=2048 hop GEMMs
    const dim3 gMid(1024 / 64, 1024 / 128);    // N=1024 hop GEMMs
    const dim3 gRu(128 / 128, 16384 / 128);    // [16384,128]+=[16384,512]@[512,128]
    const dim3 gC(64 / 64, 16384 / 128);       // [16384,64] accumulations

    for (int t = 0; t < TT; t++) {
        k_buildxh<<<(int)(SZ_NB2H / 256), 256>>>(XENC + (size_t)t * NN * BB * HH, H, X);

        sgemm<128, 128, 8, 8, 8, false><<<gBig, 256>>>(1024, 2048, 1024, AF, 1024, X,   2048, S1F, 2048);
        sgemm<128, 128, 8, 8, 8, false><<<gBig, 256>>>(1024, 2048, 1024, AF, 1024, S1F, 2048, S2F, 2048);
        sgemm<128, 128, 8, 8, 8, false><<<gBig, 256>>>(1024, 2048, 1024, AB, 1024, X,   2048, S1B, 2048);
        sgemm<128, 128, 8, 8, 8, false><<<gBig, 256>>>(1024, 2048, 1024, AB, 1024, S1B, 2048, S2B, 2048);

        k_concat_ru<<<(int)(SZ_FB / 256), 256>>>(FB, S1F, S2F, S1B, S2B);
        k_biasfill<<<(NN * BB * 128) / 256, 256>>>(PRU, BRU, 128);
        sgemm<128, 128, 8, 8, 8, true><<<gRu, 256>>>(16384, 128, 512, FB, 512, WRU, 128, PRU, 128);

        k_gates<<<(int)(SZ_NBH / 256), 256>>>(PRU, H, U, RH);

        sgemm<128, 64, 8, 8, 4, false><<<gMid, 256>>>(1024, 1024, 1024, AF, 1024, RH,  1024, T1F, 1024);
        sgemm<128, 64, 8, 8, 4, false><<<gMid, 256>>>(1024, 1024, 1024, AF, 1024, T1F, 1024, T2F, 1024);
        sgemm<128, 64, 8, 8, 4, false><<<gMid, 256>>>(1024, 1024, 1024, AB, 1024, RH,  1024, T1B, 1024);
        sgemm<128, 64, 8, 8, 4, false><<<gMid, 256>>>(1024, 1024, 1024, AB, 1024, T1B, 1024, T2B, 1024);

        k_concat_c<<<(int)(SZ_FB / 256), 256>>>(FB, S1F, T1F, S2F, T2F, S1B, T1B, S2B, T2B);
        k_biasfill<<<(int)(SZ_NBH / 256), 256>>>(PC, bc, 64);
        sgemm<128, 64, 8, 8, 4, true><<<gC, 256>>>(16384, 64, 512, FB, 512, Wc, 64, PC, 64);

        k_hupdate<<<(int)(SZ_NBH / 256), 256>>>(H, U, PC);
    }

    // ---- DiffConv readout ----
    cudaMemsetAsync(WF, 0, 2 * SZ_NN2 * sizeof(float));   // WF and WB are adjacent
    cudaMemsetAsync(DEGD, 0, 2 * NN * sizeof(float));     // DEGD and DEGS adjacent
    k_deg<<<(E + 255) / 256, 256>>>(src, dst, ew, DEGD, DEGS, E);
    k_buildW<<<(E + 255) / 256, 256>>>(src, dst, ew, DEGD, DEGS, WF, WB, E);

    sgemm<128, 64, 8, 8, 4, false><<<gMid, 256>>>(1024, 1024, 1024, WF, 1024, H,   1024, D1F, 1024);
    sgemm<128, 64, 8, 8, 4, false><<<gMid, 256>>>(1024, 1024, 1024, WF, 1024, D1F, 1024, D2F, 1024);
    sgemm<128, 64, 8, 8, 4, false><<<gMid, 256>>>(1024, 1024, 1024, WB, 1024, H,   1024, D1B, 1024);
    sgemm<128, 64, 8, 8, 4, false><<<gMid, 256>>>(1024, 1024, 1024, WB, 1024, D1B, 1024, D2B, 1024);

    k_concat_d<<<(NN * BB * 320) / 256, 256>>>(FB, H, D1F, D2F, D1B, D2B);
    k_biasfill<<<(int)(SZ_NBH / 256), 256>>>(Z, bdiff, 64);
    sgemm<128, 64, 8, 8, 4, true><<<gC, 256>>>(16384, 64, 320, FB, 320, Wdiff, 64, Z, 64);

    k_decoder<<<NN * BB, HOR * FFD>>>(Z, Wdec, bdec, out);
}